// round 7
// baseline (speedup 1.0000x reference)
#include <cuda_runtime.h>
#include <cuda_fp16.h>
#include <cstdint>

#define BDIM 1024
#define HDIM 1024
#define DIN  128
#define TLEN 16
#define BH   (BDIM*HDIM)

// ---------------- device scratch ----------------
__device__ float g_ss[BDIM], g_rs[BDIM];
__device__ __half g_x_hi[BDIM*DIN], g_x_lo[BDIM*DIN];
__device__ __half g_cT_hi[HDIM*DIN], g_cT_lo[HDIM*DIN];
__device__ __half g_WsT_hi[BH], g_WsT_lo[BH];   // lo scaled by 1024
__device__ __half g_WlT[BH], g_WrT[BH], g_WqlT[BH];
__device__ __half g_syn_hi[BH], g_syn_lo[BH];
__device__ __half g_liqA[BH], g_qA[BH];
__device__ float g_ic[BH], g_ic2[BH], g_drive[BH], g_qenh[BH];
__device__ unsigned g_sp_min[4], g_sp_max[4];
__device__ unsigned g_cp_min[128], g_cp_max[128];

// ---------------- helpers ----------------
__device__ __forceinline__ unsigned fenc(float v) {
    unsigned u = __float_as_uint(v);
    return u ^ (((int)u >> 31) | 0x80000000u);
}
__device__ __forceinline__ float fdec(unsigned k) {
    unsigned u = (k & 0x80000000u) ? (k ^ 0x80000000u) : ~k;
    return __uint_as_float(u);
}
__device__ __forceinline__ void mma16(float* d, const uint32_t* a, const uint32_t* b) {
    asm volatile("mma.sync.aligned.m16n8k16.row.col.f32.f16.f16.f32 "
                 "{%0,%1,%2,%3}, {%4,%5,%6,%7}, {%8,%9}, {%0,%1,%2,%3};"
                 : "+f"(d[0]), "+f"(d[1]), "+f"(d[2]), "+f"(d[3])
                 : "r"(a[0]), "r"(a[1]), "r"(a[2]), "r"(a[3]), "r"(b[0]), "r"(b[1]));
}
__device__ __forceinline__ int compute_noclip() {
    unsigned sn = 0xFFFFFFFFu, sx = 0u, cn = 0xFFFFFFFFu, cx = 0u;
    #pragma unroll
    for (int i = 0; i < 4; ++i) { sn = min(sn, g_sp_min[i]); sx = max(sx, g_sp_max[i]); }
    for (int i = 0; i < 128; ++i) { cn = min(cn, g_cp_min[i]); cx = max(cx, g_cp_max[i]); }
    float smin = fdec(sn), smax = fdec(sx), cmin = fdec(cn), cmax = fdec(cx);
    return (cmin + smin >= 0.1f && cmax + smax <= 3.0f) ? 1 : 0;
}
__device__ __forceinline__ void h_split(float v, __half& hi, __half& lo, float scale) {
    hi = __float2half_rn(v);
    lo = __float2half_rn((v - __half2float(hi)) * scale);
}
__device__ __forceinline__ float tanh_fast(float x) {
    float xc = fminf(fmaxf(x, -12.f), 12.f);
    float e = __expf(2.f * xc);
    return __fdividef(e - 1.f, e + 1.f);
}
#define CP_ASYNC16(dst, src) \
    asm volatile("cp.async.cg.shared.global [%0], [%1], 16;" :: "r"(dst), "l"(src))
#define CP_COMMIT() asm volatile("cp.async.commit_group;" ::: "memory")
#define CP_WAIT2()  asm volatile("cp.async.wait_group 2;" ::: "memory")

// ======================================================================
// k_prep: all independent prep in one launch, role by blockIdx.x
// ======================================================================
#define PREP_BLOCKS 9348
__global__ __launch_bounds__(256) void k_prep(const float* __restrict__ x,
                                              const float* __restrict__ liq,
                                              const float* __restrict__ q,
                                              const float* __restrict__ noise,
                                              const float* __restrict__ sh,
                                              const float* __restrict__ cond,
                                              const float* __restrict__ Ws,
                                              const float* __restrict__ Wl,
                                              const float* __restrict__ Wr,
                                              const float* __restrict__ Wql,
                                              float* __restrict__ outq) {
    __shared__ float t[32][33];
    __shared__ unsigned redn[256], redx[256];
    const int bid = blockIdx.x, tid = threadIdx.x;

    if (bid < 4) {                                  // ---- ss/rs + spike stats
        int b = bid * 256 + tid;
        float ss = 0.f;
        #pragma unroll
        for (int tt = 0; tt < TLEN; ++tt)
            ss = fmaf(sh[b * TLEN + tt], expf(-0.1f * (float)tt), ss);
        float rs = 0.f;
        for (int d = 0; d < DIN; ++d) rs += x[b * DIN + d];
        g_ss[b] = ss; g_rs[b] = rs;
        unsigned k = fenc(0.01f * ss);
        redn[tid] = k; redx[tid] = k; __syncthreads();
        for (int s = 128; s > 0; s >>= 1) {
            if (tid < s) { redn[tid] = min(redn[tid], redn[tid + s]); redx[tid] = max(redx[tid], redx[tid + s]); }
            __syncthreads();
        }
        if (tid == 0) { g_sp_min[bid] = redn[0]; g_sp_max[bid] = redx[0]; }
    } else if (bid < 132) {                         // ---- cond T+split + stats
        int i = bid - 4;
        int h0 = (i & 31) * 32, d0 = (i >> 5) * 32;
        int tx = tid & 31, ty = tid >> 5;
        float ln = 3.4e38f, lx = -3.4e38f;
        #pragma unroll
        for (int r = 0; r < 4; ++r) {
            float v = cond[(d0 + ty + 8 * r) * HDIM + h0 + tx];
            t[ty + 8 * r][tx] = v; ln = fminf(ln, v); lx = fmaxf(lx, v);
        }
        redn[tid] = fenc(ln); redx[tid] = fenc(lx); __syncthreads();
        for (int s = 128; s > 0; s >>= 1) {
            if (tid < s) { redn[tid] = min(redn[tid], redn[tid + s]); redx[tid] = max(redx[tid], redx[tid + s]); }
            __syncthreads();
        }
        if (tid == 0) { g_cp_min[i] = redn[0]; g_cp_max[i] = redx[0]; }
        #pragma unroll
        for (int r = 0; r < 4; ++r) {
            int o = (h0 + ty + 8 * r) * DIN + d0 + tx;
            h_split(t[tx][ty + 8 * r], g_cT_hi[o], g_cT_lo[o], 1.f);
        }
    } else if (bid < 4228) {                        // ---- weight transpose
        int i = bid - 132;
        int zz = i >> 10, rem = i & 1023;
        const float* W = zz == 0 ? Ws : zz == 1 ? Wl : zz == 2 ? Wr : Wql;
        int n0 = (rem & 31) * 32, k0 = (rem >> 5) * 32;
        int tx = tid & 31, ty = tid >> 5;
        #pragma unroll
        for (int r = 0; r < 4; ++r) t[ty + 8 * r][tx] = W[(k0 + ty + 8 * r) * HDIM + n0 + tx];
        __syncthreads();
        #pragma unroll
        for (int r = 0; r < 4; ++r) {
            float v = t[tx][ty + 8 * r];
            int o = (n0 + ty + 8 * r) * HDIM + k0 + tx;
            if (zz == 0) h_split(v, g_WsT_hi[o], g_WsT_lo[o], 1024.f);
            else if (zz == 1) g_WlT[o] = __float2half_rn(v);
            else if (zz == 2) g_WrT[o] = __float2half_rn(v);
            else g_WqlT[o] = __float2half_rn(v);
        }
    } else if (bid < 8324) {                        // ---- liq round + x split
        int i = (bid - 4228) * 256 + tid;
        g_liqA[i] = __float2half_rn(liq[i]);
        if (i < BDIM * DIN) h_split(x[i], g_x_hi[i], g_x_lo[i], 1.f);
    } else {                                        // ---- qnorm
        __shared__ float red[256];
        int b = bid - 8324;
        const float coh = expf(-0.00066666666666666664f);
        const float dec = 0.0015811388300841898f;
        float e[4]; float ss = 0.f;
        #pragma unroll
        for (int it = 0; it < 4; ++it) {
            int idx = b * HDIM + tid + it * 256;
            float v = q[idx] * coh + noise[idx] * dec;
            e[it] = v; ss += v * v;
        }
        red[tid] = ss; __syncthreads();
        for (int s = 128; s > 0; s >>= 1) { if (tid < s) red[tid] += red[tid + s]; __syncthreads(); }
        float den = sqrtf(red[0]) + 1e-8f;
        #pragma unroll
        for (int it = 0; it < 4; ++it) {
            int idx = b * HDIM + tid + it * 256;
            float v = e[it] / den;
            outq[idx] = v;
            g_qA[idx] = __float2half_rn(v);
        }
    }
}

// ======================================================================
// k_mma: fp16 m16n8k16, cp.async 4-stage pipeline, CTA 128x128
//   mode 0: z0 ic (2 segs -> g_ic, 1 scaled seg -> g_ic2)
//           z1 drive (2 segs -> g_drive) + qenh (1 seg -> g_qenh)
//   mode 1: syn 3-term (K=128) + rank-1 corr -> split write
// ======================================================================
#define SMH 40                         // smem stride (halfs)
#define ASZ (128 * SMH)                // halfs per operand per stage
#define SSZ (2 * ASZ)                  // halfs per stage (A + B)
#define NSTAGE 4
#define GSMEM (NSTAGE * SSZ * 2)       // bytes = 81920

__global__ __launch_bounds__(256, 1) void k_mma(int mode, const float* __restrict__ x,
                                                const float* __restrict__ cond) {
    extern __shared__ __align__(16) __half dsm[];
    __shared__ int s_noclip;
    const int tid = threadIdx.x, wid = tid >> 5, lane = tid & 31;
    const int m0 = blockIdx.y * 128, n0 = blockIdx.x * 128;
    const int wm0 = (wid & 1) * 64, wn0 = (wid >> 1) * 32;
    const int gr = lane >> 2, t4 = lane & 3;
    const int z = blockIdx.z;

    if (mode == 1) {
        if (tid == 0) s_noclip = compute_noclip();
        __syncthreads();
        if (!s_noclip) {   // exact SIMT fallback (clip binds) — correctness path
            int m = m0 + (tid & 127), nh = tid >> 7;
            float s = 0.01f * g_ss[m];
            for (int n = n0 + nh * 64; n < n0 + nh * 64 + 64; ++n) {
                float acc = 0.f;
                for (int d = 0; d < DIN; ++d)
                    acc = fmaf(x[m * DIN + d], fminf(fmaxf(cond[d * HDIM + n] + s, 0.1f), 3.0f), acc);
                size_t o = (size_t)m * HDIM + n;
                h_split(acc, g_syn_hi[o], g_syn_lo[o], 1.f);
            }
            return;
        }
    }

    const __half *Aseg[3], *Bseg[3];
    float* Cf[3] = {nullptr, nullptr, nullptr};
    int ldA, ipern;
    if (mode == 0) {
        ldA = HDIM; ipern = 32;
        if (z == 0) {
            Aseg[0] = g_syn_hi; Bseg[0] = g_WsT_hi;
            Aseg[1] = g_syn_lo; Bseg[1] = g_WsT_hi;
            Aseg[2] = g_syn_hi; Bseg[2] = g_WsT_lo;
            Cf[1] = g_ic; Cf[2] = g_ic2;
        } else {
            Aseg[0] = g_syn_hi; Bseg[0] = g_WlT;
            Aseg[1] = g_liqA;   Bseg[1] = g_WrT;
            Aseg[2] = g_qA;     Bseg[2] = g_WqlT;
            Cf[1] = g_drive; Cf[2] = g_qenh;
        }
    } else {
        ldA = DIN; ipern = 4;
        Aseg[0] = g_x_hi; Bseg[0] = g_cT_hi;
        Aseg[1] = g_x_lo; Bseg[1] = g_cT_hi;
        Aseg[2] = g_x_hi; Bseg[2] = g_cT_lo;
    }
    const int NT = 3 * ipern;

    const int lr = tid >> 2, lc8 = (tid & 3) * 8;    // 64 rows/pass, 16B chunks
    const uint32_t smem_base = (uint32_t)__cvta_generic_to_shared(dsm);
    // per-thread smem byte offsets within a stage (A and B)
    const uint32_t soA0 = (uint32_t)((lr * SMH + lc8) * 2);
    const uint32_t soA1 = (uint32_t)(((lr + 64) * SMH + lc8) * 2);

    // issue one stage's cp.asyncs (group = stage data)
    auto issue = [&](int it) {
        int seg = it / ipern, kk = (it % ipern) * 32;
        const __half* Ap = Aseg[seg];
        const __half* Bp = Bseg[seg];
        uint32_t sb = smem_base + (uint32_t)((it % NSTAGE) * SSZ * 2);
        CP_ASYNC16(sb + soA0, Ap + (size_t)(m0 + lr) * ldA + kk + lc8);
        CP_ASYNC16(sb + soA1, Ap + (size_t)(m0 + lr + 64) * ldA + kk + lc8);
        CP_ASYNC16(sb + (uint32_t)(ASZ * 2) + soA0, Bp + (size_t)(n0 + lr) * ldA + kk + lc8);
        CP_ASYNC16(sb + (uint32_t)(ASZ * 2) + soA1, Bp + (size_t)(n0 + lr + 64) * ldA + kk + lc8);
    };

    float acc[4][4][4];
    #pragma unroll
    for (int a = 0; a < 4; ++a)
        #pragma unroll
        for (int b = 0; b < 4; ++b)
            #pragma unroll
            for (int c = 0; c < 4; ++c) acc[a][b][c] = 0.f;

    // prologue: 3 stages in flight
    issue(0); CP_COMMIT();
    issue(1); CP_COMMIT();
    issue(2); CP_COMMIT();

    #pragma unroll 1
    for (int it = 0; it < NT; ++it) {
        CP_WAIT2();
        __syncthreads();                 // stage it ready; all warps past iter it-1
        if (it + 3 < NT) issue(it + 3);
        CP_COMMIT();                     // commit every iter (possibly empty group)

        const __half* As = dsm + (it % NSTAGE) * SSZ;
        const __half* Bs = As + ASZ;
        #pragma unroll
        for (int kc = 0; kc < 2; ++kc) {
            const int kb = kc * 16 + 2 * t4;
            uint32_t af[4][4], bf[4][2];
            #pragma unroll
            for (int mt = 0; mt < 4; ++mt) {
                int m = wm0 + mt * 16 + gr;
                af[mt][0] = *(const uint32_t*)&As[m * SMH + kb];
                af[mt][1] = *(const uint32_t*)&As[(m + 8) * SMH + kb];
                af[mt][2] = *(const uint32_t*)&As[m * SMH + kb + 8];
                af[mt][3] = *(const uint32_t*)&As[(m + 8) * SMH + kb + 8];
            }
            #pragma unroll
            for (int nt = 0; nt < 4; ++nt) {
                int n = wn0 + nt * 8 + gr;
                bf[nt][0] = *(const uint32_t*)&Bs[n * SMH + kb];
                bf[nt][1] = *(const uint32_t*)&Bs[n * SMH + kb + 8];
            }
            #pragma unroll
            for (int mt = 0; mt < 4; ++mt)
                #pragma unroll
                for (int nt = 0; nt < 4; ++nt)
                    mma16(acc[mt][nt], af[mt], bf[nt]);
        }
        if (mode == 0 && ((it + 1) % ipern == 0)) {
            float* C = Cf[it / ipern];
            if (C) {
                #pragma unroll
                for (int mt = 0; mt < 4; ++mt) {
                    int m = m0 + wm0 + mt * 16 + gr;
                    #pragma unroll
                    for (int nt = 0; nt < 4; ++nt) {
                        int n = n0 + wn0 + nt * 8 + t4 * 2;
                        *(float2*)(C + (size_t)m * HDIM + n) = make_float2(acc[mt][nt][0], acc[mt][nt][1]);
                        *(float2*)(C + (size_t)(m + 8) * HDIM + n) = make_float2(acc[mt][nt][2], acc[mt][nt][3]);
                    }
                }
                #pragma unroll
                for (int a = 0; a < 4; ++a)
                    #pragma unroll
                    for (int b = 0; b < 4; ++b)
                        #pragma unroll
                        for (int c = 0; c < 4; ++c) acc[a][b][c] = 0.f;
            }
        }
        __syncthreads();                 // all warps done with stage it before overwrite
    }

    if (mode == 1) {   // syn epilogue: rank-1 correction + fp16 split write
        #pragma unroll
        for (int mt = 0; mt < 4; ++mt) {
            int m = m0 + wm0 + mt * 16 + gr;
            float c0 = 0.01f * g_ss[m] * g_rs[m];
            float c1 = 0.01f * g_ss[m + 8] * g_rs[m + 8];
            #pragma unroll
            for (int nt = 0; nt < 4; ++nt) {
                int n = n0 + wn0 + nt * 8 + t4 * 2;
                #pragma unroll
                for (int e = 0; e < 4; ++e) {
                    int mm = (e < 2) ? m : m + 8;
                    float v = acc[mt][nt][e] + ((e < 2) ? c0 : c1);
                    size_t o = (size_t)mm * HDIM + n + (e & 1);
                    h_split(v, g_syn_hi[o], g_syn_lo[o], 1.f);
                }
            }
        }
    }
}

// ---------------- final fused epilogue: float4 vectorized ----------------
__global__ __launch_bounds__(256) void k_final(const float* __restrict__ mp,
                                               const float* __restrict__ refr_in,
                                               const float* __restrict__ liquid,
                                               const float* __restrict__ taup,
                                               const float* __restrict__ shist,
                                               float* __restrict__ out_fused,
                                               float* __restrict__ out_enh,
                                               float* __restrict__ out_mem,
                                               float* __restrict__ out_refr,
                                               float* __restrict__ out_hist) {
    __shared__ float wsum[8];
    const int b = blockIdx.x, tid = threadIdx.x;
    const float coh = expf(-0.00066666666666666664f);
    const int i4 = b * 256 + tid;

    float4 ic  = ((const float4*)g_ic)[i4];
    float4 ic2 = ((const float4*)g_ic2)[i4];
    float4 dr  = ((const float4*)g_drive)[i4];
    float4 qe  = ((const float4*)g_qenh)[i4];
    float4 mpv = ((const float4*)mp)[i4];
    float4 rf  = ((const float4*)refr_in)[i4];
    float4 lq  = ((const float4*)liquid)[i4];
    float4 tp  = ((const float4*)taup)[tid];

    float4 omem, orefr, oenh, ofused;
    float ssum = 0.f;
    #pragma unroll
    for (int e = 0; e < 4; ++e) {
        float icv = ((const float*)&ic)[e] + 9.765625e-4f * ((const float*)&ic2)[e];
        float r = fmaxf(((const float*)&rf)[e] - 0.1f, 0.f);
        bool act = (r == 0.f);
        float mem = ((const float*)&mpv)[e] * 0.95f + (act ? icv * 0.1f : 0.f);
        bool sp = (mem > 0.8f) && act;
        float spike = sp ? 1.f : 0.f;
        ((float*)&omem)[e] = sp ? 0.f : mem;
        ((float*)&orefr)[e] = sp ? 2.f : r;
        float sig = __fdividef(1.f, 1.f + __expf(-((const float*)&tp)[e]));
        float tau = 2.f + 23.f * sig;
        float l = ((const float*)&lq)[e];
        float nl = l + 0.1f * (tanh_fast(((const float*)&dr)[e]) - l) * __fdividef(1.f, tau);
        float enh = nl + 0.1f * (((const float*)&qe)[e] * coh * 0.85f);
        ((float*)&oenh)[e] = enh;
        ((float*)&ofused)[e] = spike * (1.f + 0.1f * tanh_fast(enh));
        ssum += spike;
    }
    ((float4*)out_mem)[i4] = omem;
    ((float4*)out_refr)[i4] = orefr;
    ((float4*)out_enh)[i4] = oenh;
    ((float4*)out_fused)[i4] = ofused;

    #pragma unroll
    for (int o = 16; o; o >>= 1) ssum += __shfl_xor_sync(~0u, ssum, o);
    if ((tid & 31) == 0) wsum[tid >> 5] = ssum;
    __syncthreads();
    if (tid < TLEN - 1) {
        out_hist[b * TLEN + tid] = shist[b * TLEN + tid + 1];
    } else if (tid == TLEN - 1) {
        float t = 0.f;
        #pragma unroll
        for (int i = 0; i < 8; ++i) t += wsum[i];
        out_hist[b * TLEN + TLEN - 1] = t * (1.0f / 1024.0f);
    }
}

// ---------------- launch ----------------
extern "C" void kernel_launch(void* const* d_in, const int* in_sizes, int n_in,
                              void* d_out, int out_size) {
    const float* x      = (const float*)d_in[0];
    const float* liquid = (const float*)d_in[1];
    const float* qstate = (const float*)d_in[2];
    const float* mp     = (const float*)d_in[3];
    const float* refr   = (const float*)d_in[4];
    const float* shist  = (const float*)d_in[5];
    const float* noise  = (const float*)d_in[6];
    const float* cond   = (const float*)d_in[7];
    const float* taup   = (const float*)d_in[8];
    const float* W_l    = (const float*)d_in[9];
    const float* W_r    = (const float*)d_in[10];
    const float* W_s    = (const float*)d_in[11];
    const float* W_ql   = (const float*)d_in[12];

    float* out       = (float*)d_out;
    float* out_fused = out;
    float* out_enh   = out + (size_t)BH;
    float* out_q     = out + (size_t)2 * BH;
    float* out_mem   = out + (size_t)3 * BH;
    float* out_refr  = out + (size_t)4 * BH;
    float* out_hist  = out + (size_t)5 * BH;

    static int smem_set = 0;
    if (!smem_set) {
        cudaFuncSetAttribute(k_mma, cudaFuncAttributeMaxDynamicSharedMemorySize, GSMEM);
        smem_set = 1;
    }

    k_prep<<<PREP_BLOCKS, 256>>>(x, liquid, qstate, noise, shist, cond,
                                 W_s, W_l, W_r, W_ql, out_q);
    k_mma<<<dim3(8, 8), 256, GSMEM>>>(1, x, cond);
    k_mma<<<dim3(8, 8, 2), 256, GSMEM>>>(0, x, cond);
    k_final<<<BDIM, 256>>>(mp, refr, liquid, taup, shist,
                           out_fused, out_enh, out_mem, out_refr, out_hist);
}

// round 10
// speedup vs baseline: 1.6702x; 1.6702x over previous
#include <cuda_runtime.h>
#include <cuda_fp16.h>
#include <cstdint>

#define BDIM 1024
#define HDIM 1024
#define DIN  128
#define TLEN 16
#define BH   (BDIM*HDIM)

// ---------------- device scratch ----------------
__device__ float g_ss[BDIM], g_rs[BDIM];
__device__ __half g_x_hi[BDIM*DIN], g_x_lo[BDIM*DIN];
__device__ __half g_cT_hi[HDIM*DIN], g_cT_lo[HDIM*DIN];
__device__ __half g_WsT_hi[BH], g_WsT_lo[BH];   // lo scaled by 1024
__device__ __half g_WlT[BH], g_WrT[BH], g_WqlT[BH];
__device__ __half g_syn_hi[BH], g_syn_lo[BH];
__device__ __half g_liqA[BH], g_qA[BH];
__device__ float g_ic[BH], g_ic2[BH], g_drive[BH], g_qenh[BH];
__device__ unsigned g_sp_min[4], g_sp_max[4];
__device__ unsigned g_cp_min[128], g_cp_max[128];

// ---------------- helpers ----------------
__device__ __forceinline__ unsigned fenc(float v) {
    unsigned u = __float_as_uint(v);
    return u ^ (((int)u >> 31) | 0x80000000u);
}
__device__ __forceinline__ float fdec(unsigned k) {
    unsigned u = (k & 0x80000000u) ? (k ^ 0x80000000u) : ~k;
    return __uint_as_float(u);
}
__device__ __forceinline__ void mma16(float* d, const uint32_t* a, const uint32_t* b) {
    asm volatile("mma.sync.aligned.m16n8k16.row.col.f32.f16.f16.f32 "
                 "{%0,%1,%2,%3}, {%4,%5,%6,%7}, {%8,%9}, {%0,%1,%2,%3};"
                 : "+f"(d[0]), "+f"(d[1]), "+f"(d[2]), "+f"(d[3])
                 : "r"(a[0]), "r"(a[1]), "r"(a[2]), "r"(a[3]), "r"(b[0]), "r"(b[1]));
}
__device__ __forceinline__ void ldsm4(uint32_t& r0, uint32_t& r1, uint32_t& r2, uint32_t& r3,
                                      uint32_t addr) {
    asm volatile("ldmatrix.sync.aligned.m8n8.x4.shared.b16 {%0,%1,%2,%3}, [%4];"
                 : "=r"(r0), "=r"(r1), "=r"(r2), "=r"(r3) : "r"(addr));
}
__device__ __forceinline__ void h_split(float v, __half& hi, __half& lo, float scale) {
    hi = __float2half_rn(v);
    lo = __float2half_rn((v - __half2float(hi)) * scale);
}
__device__ __forceinline__ float tanh_fast(float x) {
    float xc = fminf(fmaxf(x, -12.f), 12.f);
    float e = __expf(2.f * xc);
    return __fdividef(e - 1.f, e + 1.f);
}
// warp-parallel noclip check (lane-distributed loads + shuffle reduce)
__device__ __forceinline__ int compute_noclip_warp(int lane) {
    unsigned sn = 0xFFFFFFFFu, sx = 0u, cn = 0xFFFFFFFFu, cx = 0u;
    if (lane < 4) { sn = g_sp_min[lane]; sx = g_sp_max[lane]; }
    #pragma unroll
    for (int i = 0; i < 4; ++i) {
        cn = min(cn, g_cp_min[lane + 32 * i]);
        cx = max(cx, g_cp_max[lane + 32 * i]);
    }
    #pragma unroll
    for (int o = 16; o; o >>= 1) {
        sn = min(sn, __shfl_xor_sync(~0u, sn, o));
        sx = max(sx, __shfl_xor_sync(~0u, sx, o));
        cn = min(cn, __shfl_xor_sync(~0u, cn, o));
        cx = max(cx, __shfl_xor_sync(~0u, cx, o));
    }
    float smin = fdec(sn), smax = fdec(sx), cmin = fdec(cn), cmax = fdec(cx);
    return (cmin + smin >= 0.1f && cmax + smax <= 3.0f) ? 1 : 0;
}

// ======================================================================
// k_prep: all independent prep in one launch, role by blockIdx.x
// ======================================================================
#define PREP_BLOCKS 9348
__global__ __launch_bounds__(256) void k_prep(const float* __restrict__ x,
                                              const float* __restrict__ liq,
                                              const float* __restrict__ q,
                                              const float* __restrict__ noise,
                                              const float* __restrict__ sh,
                                              const float* __restrict__ cond,
                                              const float* __restrict__ Ws,
                                              const float* __restrict__ Wl,
                                              const float* __restrict__ Wr,
                                              const float* __restrict__ Wql,
                                              float* __restrict__ outq) {
    __shared__ float t[32][33];
    __shared__ unsigned redn[256], redx[256];
    const int bid = blockIdx.x, tid = threadIdx.x;

    if (bid < 4) {                                  // ---- ss/rs + spike stats
        int b = bid * 256 + tid;
        float ss = 0.f;
        #pragma unroll
        for (int tt = 0; tt < TLEN; ++tt)
            ss = fmaf(sh[b * TLEN + tt], expf(-0.1f * (float)tt), ss);
        float rs = 0.f;
        for (int d = 0; d < DIN; ++d) rs += x[b * DIN + d];
        g_ss[b] = ss; g_rs[b] = rs;
        unsigned k = fenc(0.01f * ss);
        redn[tid] = k; redx[tid] = k; __syncthreads();
        for (int s = 128; s > 0; s >>= 1) {
            if (tid < s) { redn[tid] = min(redn[tid], redn[tid + s]); redx[tid] = max(redx[tid], redx[tid + s]); }
            __syncthreads();
        }
        if (tid == 0) { g_sp_min[bid] = redn[0]; g_sp_max[bid] = redx[0]; }
    } else if (bid < 132) {                         // ---- cond T+split + stats
        int i = bid - 4;
        int h0 = (i & 31) * 32, d0 = (i >> 5) * 32;
        int tx = tid & 31, ty = tid >> 5;
        float ln = 3.4e38f, lx = -3.4e38f;
        #pragma unroll
        for (int r = 0; r < 4; ++r) {
            float v = cond[(d0 + ty + 8 * r) * HDIM + h0 + tx];
            t[ty + 8 * r][tx] = v; ln = fminf(ln, v); lx = fmaxf(lx, v);
        }
        redn[tid] = fenc(ln); redx[tid] = fenc(lx); __syncthreads();
        for (int s = 128; s > 0; s >>= 1) {
            if (tid < s) { redn[tid] = min(redn[tid], redn[tid + s]); redx[tid] = max(redx[tid], redx[tid + s]); }
            __syncthreads();
        }
        if (tid == 0) { g_cp_min[i] = redn[0]; g_cp_max[i] = redx[0]; }
        #pragma unroll
        for (int r = 0; r < 4; ++r) {
            int o = (h0 + ty + 8 * r) * DIN + d0 + tx;
            h_split(t[tx][ty + 8 * r], g_cT_hi[o], g_cT_lo[o], 1.f);
        }
    } else if (bid < 4228) {                        // ---- weight transpose
        int i = bid - 132;
        int zz = i >> 10, rem = i & 1023;
        const float* W = zz == 0 ? Ws : zz == 1 ? Wl : zz == 2 ? Wr : Wql;
        int n0 = (rem & 31) * 32, k0 = (rem >> 5) * 32;
        int tx = tid & 31, ty = tid >> 5;
        #pragma unroll
        for (int r = 0; r < 4; ++r) t[ty + 8 * r][tx] = W[(k0 + ty + 8 * r) * HDIM + n0 + tx];
        __syncthreads();
        #pragma unroll
        for (int r = 0; r < 4; ++r) {
            float v = t[tx][ty + 8 * r];
            int o = (n0 + ty + 8 * r) * HDIM + k0 + tx;
            if (zz == 0) h_split(v, g_WsT_hi[o], g_WsT_lo[o], 1024.f);
            else if (zz == 1) g_WlT[o] = __float2half_rn(v);
            else if (zz == 2) g_WrT[o] = __float2half_rn(v);
            else g_WqlT[o] = __float2half_rn(v);
        }
    } else if (bid < 8324) {                        // ---- liq round + x split
        int i = (bid - 4228) * 256 + tid;
        g_liqA[i] = __float2half_rn(liq[i]);
        if (i < BDIM * DIN) h_split(x[i], g_x_hi[i], g_x_lo[i], 1.f);
    } else {                                        // ---- qnorm
        __shared__ float red[256];
        int b = bid - 8324;
        const float coh = expf(-0.00066666666666666664f);
        const float dec = 0.0015811388300841898f;
        float e[4]; float ss = 0.f;
        #pragma unroll
        for (int it = 0; it < 4; ++it) {
            int idx = b * HDIM + tid + it * 256;
            float v = q[idx] * coh + noise[idx] * dec;
            e[it] = v; ss += v * v;
        }
        red[tid] = ss; __syncthreads();
        for (int s = 128; s > 0; s >>= 1) { if (tid < s) red[tid] += red[tid + s]; __syncthreads(); }
        float den = sqrtf(red[0]) + 1e-8f;
        #pragma unroll
        for (int it = 0; it < 4; ++it) {
            int idx = b * HDIM + tid + it * 256;
            float v = e[it] / den;
            outq[idx] = v;
            g_qA[idx] = __float2half_rn(v);
        }
    }
}

// ======================================================================
// k_mma: fp16 m16n8k16, register double-buffer + ldmatrix fragments
//   mode 0: z0 ic (2 segs -> g_ic, 1 scaled seg -> g_ic2)
//           z1 drive (2 segs -> g_drive) + qenh (1 seg -> g_qenh)
//   mode 1: syn 3-term (K=128) + rank-1 corr -> split write
// ======================================================================
#define SMH 40   // smem stride in halfs (conflict-free for STS / LDSM phases)

__global__ __launch_bounds__(256, 1) void k_mma(int mode, const float* __restrict__ x,
                                                const float* __restrict__ cond) {
    __shared__ __align__(16) __half smA[2][128 * SMH];
    __shared__ __align__(16) __half smB[2][128 * SMH];
    __shared__ int s_noclip;
    const int tid = threadIdx.x, wid = tid >> 5, lane = tid & 31;
    const int m0 = blockIdx.y * 128, n0 = blockIdx.x * 128;
    const int wm0 = (wid & 1) * 64, wn0 = (wid >> 1) * 32;
    const int gr = lane >> 2, t4 = lane & 3;
    const int z = blockIdx.z;

    if (mode == 1) {
        if (wid == 0) {
            int nc = compute_noclip_warp(lane);
            if (lane == 0) s_noclip = nc;
        }
        __syncthreads();
        if (!s_noclip) {   // exact SIMT fallback (clip binds) — correctness path
            int m = m0 + (tid & 127), nh = tid >> 7;
            float s = 0.01f * g_ss[m];
            for (int n = n0 + nh * 64; n < n0 + nh * 64 + 64; ++n) {
                float acc = 0.f;
                for (int d = 0; d < DIN; ++d)
                    acc = fmaf(x[m * DIN + d], fminf(fmaxf(cond[d * HDIM + n] + s, 0.1f), 3.0f), acc);
                size_t o = (size_t)m * HDIM + n;
                h_split(acc, g_syn_hi[o], g_syn_lo[o], 1.f);
            }
            return;
        }
    }

    const __half *Aseg[3], *Bseg[3];
    float* Cf[3] = {nullptr, nullptr, nullptr};
    int ldA, ipern;
    if (mode == 0) {
        ldA = HDIM; ipern = 32;
        if (z == 0) {
            Aseg[0] = g_syn_hi; Bseg[0] = g_WsT_hi;
            Aseg[1] = g_syn_lo; Bseg[1] = g_WsT_hi;
            Aseg[2] = g_syn_hi; Bseg[2] = g_WsT_lo;
            Cf[1] = g_ic; Cf[2] = g_ic2;
        } else {
            Aseg[0] = g_syn_hi; Bseg[0] = g_WlT;
            Aseg[1] = g_liqA;   Bseg[1] = g_WrT;
            Aseg[2] = g_qA;     Bseg[2] = g_WqlT;
            Cf[1] = g_drive; Cf[2] = g_qenh;
        }
    } else {
        ldA = DIN; ipern = 4;
        Aseg[0] = g_x_hi; Bseg[0] = g_cT_hi;
        Aseg[1] = g_x_lo; Bseg[1] = g_cT_hi;
        Aseg[2] = g_x_hi; Bseg[2] = g_cT_lo;
    }
    const int NT = 3 * ipern;

    // ldmatrix per-lane base addresses (byte, shared space)
    const uint32_t baseA = (uint32_t)__cvta_generic_to_shared(&smA[0][0]);
    const uint32_t baseB = (uint32_t)__cvta_generic_to_shared(&smB[0][0]);
    const uint32_t bufStride = (uint32_t)(128 * SMH * 2);
    // A: row = wm0 + (lane&15), kOff = 8*(lane>>4)
    const uint32_t aLane = (uint32_t)(((wm0 + (lane & 15)) * SMH + 8 * (lane >> 4)) * 2);
    // B: row = wn0 + 8*(lane>>4) + (lane&7), kOff = 8*((lane>>3)&1)
    const uint32_t bLane = (uint32_t)(((wn0 + 8 * (lane >> 4) + (lane & 7)) * SMH + 8 * ((lane >> 3) & 1)) * 2);

    float acc[4][4][4];
    #pragma unroll
    for (int a = 0; a < 4; ++a)
        #pragma unroll
        for (int b = 0; b < 4; ++b)
            #pragma unroll
            for (int c = 0; c < 4; ++c) acc[a][b][c] = 0.f;

    const int lr = tid >> 2, lc8 = (tid & 3) * 8;    // 64 rows/pass, 8-half cols
    uint4 ra[2], rb[2];
    {   // iter 0 -> buffer 0
        #pragma unroll
        for (int i = 0; i < 2; ++i) {
            int r = lr + i * 64;
            ra[i] = *(const uint4*)(Aseg[0] + (size_t)(m0 + r) * ldA + lc8);
            rb[i] = *(const uint4*)(Bseg[0] + (size_t)(n0 + r) * ldA + lc8);
        }
        #pragma unroll
        for (int i = 0; i < 2; ++i) {
            int r = lr + i * 64;
            *(uint4*)&smA[0][r * SMH + lc8] = ra[i];
            *(uint4*)&smB[0][r * SMH + lc8] = rb[i];
        }
    }
    __syncthreads();

    #pragma unroll 1
    for (int it = 0; it < NT; ++it) {
        const int cur = it & 1;
        const uint32_t aBuf = baseA + cur * bufStride + aLane;
        const uint32_t bBuf = baseB + cur * bufStride + bLane;
        if (it + 1 < NT) {
            int seg = (it + 1) / ipern, kk = ((it + 1) % ipern) * 32;
            #pragma unroll
            for (int i = 0; i < 2; ++i) {
                int r = lr + i * 64;
                ra[i] = *(const uint4*)(Aseg[seg] + (size_t)(m0 + r) * ldA + kk + lc8);
                rb[i] = *(const uint4*)(Bseg[seg] + (size_t)(n0 + r) * ldA + kk + lc8);
            }
        }
        #pragma unroll
        for (int kc = 0; kc < 2; ++kc) {
            const uint32_t kOff = (uint32_t)(kc * 32);   // 16 halfs = 32 bytes
            uint32_t af[4][4], bf[4][2];
            #pragma unroll
            for (int mt = 0; mt < 4; ++mt)
                ldsm4(af[mt][0], af[mt][1], af[mt][2], af[mt][3],
                      aBuf + (uint32_t)(mt * 16 * SMH * 2) + kOff);
            ldsm4(bf[0][0], bf[0][1], bf[1][0], bf[1][1], bBuf + kOff);
            ldsm4(bf[2][0], bf[2][1], bf[3][0], bf[3][1],
                  bBuf + (uint32_t)(16 * SMH * 2) + kOff);
            #pragma unroll
            for (int mt = 0; mt < 4; ++mt)
                #pragma unroll
                for (int nt = 0; nt < 4; ++nt)
                    mma16(acc[mt][nt], af[mt], bf[nt]);
        }
        if (mode == 0 && ((it + 1) % ipern == 0)) {
            float* C = Cf[it / ipern];
            if (C) {
                #pragma unroll
                for (int mt = 0; mt < 4; ++mt) {
                    int m = m0 + wm0 + mt * 16 + gr;
                    #pragma unroll
                    for (int nt = 0; nt < 4; ++nt) {
                        int n = n0 + wn0 + nt * 8 + t4 * 2;
                        *(float2*)(C + (size_t)m * HDIM + n) = make_float2(acc[mt][nt][0], acc[mt][nt][1]);
                        *(float2*)(C + (size_t)(m + 8) * HDIM + n) = make_float2(acc[mt][nt][2], acc[mt][nt][3]);
                    }
                }
                #pragma unroll
                for (int a = 0; a < 4; ++a)
                    #pragma unroll
                    for (int b = 0; b < 4; ++b)
                        #pragma unroll
                        for (int c = 0; c < 4; ++c) acc[a][b][c] = 0.f;
            }
        }
        if (it + 1 < NT) {
            #pragma unroll
            for (int i = 0; i < 2; ++i) {
                int r = lr + i * 64;
                *(uint4*)&smA[cur ^ 1][r * SMH + lc8] = ra[i];
                *(uint4*)&smB[cur ^ 1][r * SMH + lc8] = rb[i];
            }
        }
        __syncthreads();
    }

    if (mode == 1) {   // syn epilogue: rank-1 correction + fp16 split write
        #pragma unroll
        for (int mt = 0; mt < 4; ++mt) {
            int m = m0 + wm0 + mt * 16 + gr;
            float c0 = 0.01f * g_ss[m] * g_rs[m];
            float c1 = 0.01f * g_ss[m + 8] * g_rs[m + 8];
            #pragma unroll
            for (int nt = 0; nt < 4; ++nt) {
                int n = n0 + wn0 + nt * 8 + t4 * 2;
                #pragma unroll
                for (int e = 0; e < 4; ++e) {
                    int mm = (e < 2) ? m : m + 8;
                    float v = acc[mt][nt][e] + ((e < 2) ? c0 : c1);
                    size_t o = (size_t)mm * HDIM + n + (e & 1);
                    h_split(v, g_syn_hi[o], g_syn_lo[o], 1.f);
                }
            }
        }
    }
}

// ---------------- final fused epilogue: float4 vectorized ----------------
__global__ __launch_bounds__(256) void k_final(const float* __restrict__ mp,
                                               const float* __restrict__ refr_in,
                                               const float* __restrict__ liquid,
                                               const float* __restrict__ taup,
                                               const float* __restrict__ shist,
                                               float* __restrict__ out_fused,
                                               float* __restrict__ out_enh,
                                               float* __restrict__ out_mem,
                                               float* __restrict__ out_refr,
                                               float* __restrict__ out_hist) {
    __shared__ float wsum[8];
    const int b = blockIdx.x, tid = threadIdx.x;
    const float coh = expf(-0.00066666666666666664f);
    const int i4 = b * 256 + tid;

    float4 ic  = ((const float4*)g_ic)[i4];
    float4 ic2 = ((const float4*)g_ic2)[i4];
    float4 dr  = ((const float4*)g_drive)[i4];
    float4 qe  = ((const float4*)g_qenh)[i4];
    float4 mpv = ((const float4*)mp)[i4];
    float4 rf  = ((const float4*)refr_in)[i4];
    float4 lq  = ((const float4*)liquid)[i4];
    float4 tp  = ((const float4*)taup)[tid];

    float4 omem, orefr, oenh, ofused;
    float ssum = 0.f;
    #pragma unroll
    for (int e = 0; e < 4; ++e) {
        float icv = ((const float*)&ic)[e] + 9.765625e-4f * ((const float*)&ic2)[e];
        float r = fmaxf(((const float*)&rf)[e] - 0.1f, 0.f);
        bool act = (r == 0.f);
        float mem = ((const float*)&mpv)[e] * 0.95f + (act ? icv * 0.1f : 0.f);
        bool sp = (mem > 0.8f) && act;
        float spike = sp ? 1.f : 0.f;
        ((float*)&omem)[e] = sp ? 0.f : mem;
        ((float*)&orefr)[e] = sp ? 2.f : r;
        float sig = __fdividef(1.f, 1.f + __expf(-((const float*)&tp)[e]));
        float tau = 2.f + 23.f * sig;
        float l = ((const float*)&lq)[e];
        float nl = l + 0.1f * (tanh_fast(((const float*)&dr)[e]) - l) * __fdividef(1.f, tau);
        float enh = nl + 0.1f * (((const float*)&qe)[e] * coh * 0.85f);
        ((float*)&oenh)[e] = enh;
        ((float*)&ofused)[e] = spike * (1.f + 0.1f * tanh_fast(enh));
        ssum += spike;
    }
    ((float4*)out_mem)[i4] = omem;
    ((float4*)out_refr)[i4] = orefr;
    ((float4*)out_enh)[i4] = oenh;
    ((float4*)out_fused)[i4] = ofused;

    #pragma unroll
    for (int o = 16; o; o >>= 1) ssum += __shfl_xor_sync(~0u, ssum, o);
    if ((tid & 31) == 0) wsum[tid >> 5] = ssum;
    __syncthreads();
    if (tid < TLEN - 1) {
        out_hist[b * TLEN + tid] = shist[b * TLEN + tid + 1];
    } else if (tid == TLEN - 1) {
        float t = 0.f;
        #pragma unroll
        for (int i = 0; i < 8; ++i) t += wsum[i];
        out_hist[b * TLEN + TLEN - 1] = t * (1.0f / 1024.0f);
    }
}

// ---------------- launch ----------------
extern "C" void kernel_launch(void* const* d_in, const int* in_sizes, int n_in,
                              void* d_out, int out_size) {
    const float* x      = (const float*)d_in[0];
    const float* liquid = (const float*)d_in[1];
    const float* qstate = (const float*)d_in[2];
    const float* mp     = (const float*)d_in[3];
    const float* refr   = (const float*)d_in[4];
    const float* shist  = (const float*)d_in[5];
    const float* noise  = (const float*)d_in[6];
    const float* cond   = (const float*)d_in[7];
    const float* taup   = (const float*)d_in[8];
    const float* W_l    = (const float*)d_in[9];
    const float* W_r    = (const float*)d_in[10];
    const float* W_s    = (const float*)d_in[11];
    const float* W_ql   = (const float*)d_in[12];

    float* out       = (float*)d_out;
    float* out_fused = out;
    float* out_enh   = out + (size_t)BH;
    float* out_q     = out + (size_t)2 * BH;
    float* out_mem   = out + (size_t)3 * BH;
    float* out_refr  = out + (size_t)4 * BH;
    float* out_hist  = out + (size_t)5 * BH;

    k_prep<<<PREP_BLOCKS, 256>>>(x, liquid, qstate, noise, shist, cond,
                                 W_s, W_l, W_r, W_ql, out_q);
    k_mma<<<dim3(8, 8), 256>>>(1, x, cond);
    k_mma<<<dim3(8, 8, 2), 256>>>(0, x, cond);
    k_final<<<BDIM, 256>>>(mp, refr, liquid, taup, shist,
                           out_fused, out_enh, out_mem, out_refr, out_hist);
}

// round 11
// speedup vs baseline: 1.8682x; 1.1185x over previous
#include <cuda_runtime.h>
#include <cuda_fp16.h>
#include <cstdint>

#define BDIM 1024
#define HDIM 1024
#define DIN  128
#define TLEN 16
#define BH   (BDIM*HDIM)

// ---------------- device scratch ----------------
__device__ float g_ss[BDIM], g_rs[BDIM];
__device__ __half g_x_hi[BDIM*DIN], g_x_lo[BDIM*DIN];
__device__ __half g_cT_hi[HDIM*DIN], g_cT_lo[HDIM*DIN];
__device__ __half g_WsT_hi[BH], g_WsT_lo[BH];   // lo scaled by 1024
__device__ __half g_WlT[BH], g_WrT[BH], g_WqlT[BH];
__device__ __half g_syn_hi[BH], g_syn_lo[BH];
__device__ __half g_liqA[BH], g_qA[BH];
__device__ float g_ic[BH], g_ic2[BH], g_drive[BH], g_qenh[BH];
__device__ unsigned g_sp_min[4], g_sp_max[4];
__device__ unsigned g_cp_min[128], g_cp_max[128];

// ---------------- helpers ----------------
__device__ __forceinline__ unsigned fenc(float v) {
    unsigned u = __float_as_uint(v);
    return u ^ (((int)u >> 31) | 0x80000000u);
}
__device__ __forceinline__ float fdec(unsigned k) {
    unsigned u = (k & 0x80000000u) ? (k ^ 0x80000000u) : ~k;
    return __uint_as_float(u);
}
__device__ __forceinline__ void mma16(float* d, const uint32_t* a, const uint32_t* b) {
    asm volatile("mma.sync.aligned.m16n8k16.row.col.f32.f16.f16.f32 "
                 "{%0,%1,%2,%3}, {%4,%5,%6,%7}, {%8,%9}, {%0,%1,%2,%3};"
                 : "+f"(d[0]), "+f"(d[1]), "+f"(d[2]), "+f"(d[3])
                 : "r"(a[0]), "r"(a[1]), "r"(a[2]), "r"(a[3]), "r"(b[0]), "r"(b[1]));
}
__device__ __forceinline__ void ldsm4(uint32_t& r0, uint32_t& r1, uint32_t& r2, uint32_t& r3,
                                      uint32_t addr) {
    asm volatile("ldmatrix.sync.aligned.m8n8.x4.shared.b16 {%0,%1,%2,%3}, [%4];"
                 : "=r"(r0), "=r"(r1), "=r"(r2), "=r"(r3) : "r"(addr));
}
__device__ __forceinline__ void h_split(float v, __half& hi, __half& lo, float scale) {
    hi = __float2half_rn(v);
    lo = __float2half_rn((v - __half2float(hi)) * scale);
}
__device__ __forceinline__ float tanh_fast(float x) {
    float xc = fminf(fmaxf(x, -12.f), 12.f);
    float e = __expf(2.f * xc);
    return __fdividef(e - 1.f, e + 1.f);
}
// warp-parallel noclip check (lane-distributed loads + shuffle reduce)
__device__ __forceinline__ int compute_noclip_warp(int lane) {
    unsigned sn = 0xFFFFFFFFu, sx = 0u, cn = 0xFFFFFFFFu, cx = 0u;
    if (lane < 4) { sn = g_sp_min[lane]; sx = g_sp_max[lane]; }
    #pragma unroll
    for (int i = 0; i < 4; ++i) {
        cn = min(cn, g_cp_min[lane + 32 * i]);
        cx = max(cx, g_cp_max[lane + 32 * i]);
    }
    #pragma unroll
    for (int o = 16; o; o >>= 1) {
        sn = min(sn, __shfl_xor_sync(~0u, sn, o));
        sx = max(sx, __shfl_xor_sync(~0u, sx, o));
        cn = min(cn, __shfl_xor_sync(~0u, cn, o));
        cx = max(cx, __shfl_xor_sync(~0u, cx, o));
    }
    float smin = fdec(sn), smax = fdec(sx), cmin = fdec(cn), cmax = fdec(cx);
    return (cmin + smin >= 0.1f && cmax + smax <= 3.0f) ? 1 : 0;
}

// ======================================================================
// k_prep: all independent prep in one launch, role by blockIdx.x
// ======================================================================
#define PREP_BLOCKS 9348
__global__ __launch_bounds__(256) void k_prep(const float* __restrict__ x,
                                              const float* __restrict__ liq,
                                              const float* __restrict__ q,
                                              const float* __restrict__ noise,
                                              const float* __restrict__ sh,
                                              const float* __restrict__ cond,
                                              const float* __restrict__ Ws,
                                              const float* __restrict__ Wl,
                                              const float* __restrict__ Wr,
                                              const float* __restrict__ Wql,
                                              float* __restrict__ outq) {
    __shared__ float t[32][33];
    __shared__ unsigned redn[256], redx[256];
    const int bid = blockIdx.x, tid = threadIdx.x;

    if (bid < 4) {                                  // ---- ss/rs + spike stats
        int b = bid * 256 + tid;
        float ss = 0.f;
        #pragma unroll
        for (int tt = 0; tt < TLEN; ++tt)
            ss = fmaf(sh[b * TLEN + tt], expf(-0.1f * (float)tt), ss);
        float rs = 0.f;
        for (int d = 0; d < DIN; ++d) rs += x[b * DIN + d];
        g_ss[b] = ss; g_rs[b] = rs;
        unsigned k = fenc(0.01f * ss);
        redn[tid] = k; redx[tid] = k; __syncthreads();
        for (int s = 128; s > 0; s >>= 1) {
            if (tid < s) { redn[tid] = min(redn[tid], redn[tid + s]); redx[tid] = max(redx[tid], redx[tid + s]); }
            __syncthreads();
        }
        if (tid == 0) { g_sp_min[bid] = redn[0]; g_sp_max[bid] = redx[0]; }
    } else if (bid < 132) {                         // ---- cond T+split + stats
        int i = bid - 4;
        int h0 = (i & 31) * 32, d0 = (i >> 5) * 32;
        int tx = tid & 31, ty = tid >> 5;
        float ln = 3.4e38f, lx = -3.4e38f;
        #pragma unroll
        for (int r = 0; r < 4; ++r) {
            float v = cond[(d0 + ty + 8 * r) * HDIM + h0 + tx];
            t[ty + 8 * r][tx] = v; ln = fminf(ln, v); lx = fmaxf(lx, v);
        }
        redn[tid] = fenc(ln); redx[tid] = fenc(lx); __syncthreads();
        for (int s = 128; s > 0; s >>= 1) {
            if (tid < s) { redn[tid] = min(redn[tid], redn[tid + s]); redx[tid] = max(redx[tid], redx[tid + s]); }
            __syncthreads();
        }
        if (tid == 0) { g_cp_min[i] = redn[0]; g_cp_max[i] = redx[0]; }
        #pragma unroll
        for (int r = 0; r < 4; ++r) {
            int o = (h0 + ty + 8 * r) * DIN + d0 + tx;
            h_split(t[tx][ty + 8 * r], g_cT_hi[o], g_cT_lo[o], 1.f);
        }
    } else if (bid < 4228) {                        // ---- weight transpose
        int i = bid - 132;
        int zz = i >> 10, rem = i & 1023;
        const float* W = zz == 0 ? Ws : zz == 1 ? Wl : zz == 2 ? Wr : Wql;
        int n0 = (rem & 31) * 32, k0 = (rem >> 5) * 32;
        int tx = tid & 31, ty = tid >> 5;
        #pragma unroll
        for (int r = 0; r < 4; ++r) t[ty + 8 * r][tx] = W[(k0 + ty + 8 * r) * HDIM + n0 + tx];
        __syncthreads();
        #pragma unroll
        for (int r = 0; r < 4; ++r) {
            float v = t[tx][ty + 8 * r];
            int o = (n0 + ty + 8 * r) * HDIM + k0 + tx;
            if (zz == 0) h_split(v, g_WsT_hi[o], g_WsT_lo[o], 1024.f);
            else if (zz == 1) g_WlT[o] = __float2half_rn(v);
            else if (zz == 2) g_WrT[o] = __float2half_rn(v);
            else g_WqlT[o] = __float2half_rn(v);
        }
    } else if (bid < 8324) {                        // ---- liq round + x split
        int i = (bid - 4228) * 256 + tid;
        g_liqA[i] = __float2half_rn(liq[i]);
        if (i < BDIM * DIN) h_split(x[i], g_x_hi[i], g_x_lo[i], 1.f);
    } else {                                        // ---- qnorm
        __shared__ float red[256];
        int b = bid - 8324;
        const float coh = expf(-0.00066666666666666664f);
        const float dec = 0.0015811388300841898f;
        float e[4]; float ss = 0.f;
        #pragma unroll
        for (int it = 0; it < 4; ++it) {
            int idx = b * HDIM + tid + it * 256;
            float v = q[idx] * coh + noise[idx] * dec;
            e[it] = v; ss += v * v;
        }
        red[tid] = ss; __syncthreads();
        for (int s = 128; s > 0; s >>= 1) { if (tid < s) red[tid] += red[tid + s]; __syncthreads(); }
        float den = sqrtf(red[0]) + 1e-8f;
        #pragma unroll
        for (int it = 0; it < 4; ++it) {
            int idx = b * HDIM + tid + it * 256;
            float v = e[it] / den;
            outq[idx] = v;
            g_qA[idx] = __float2half_rn(v);
        }
    }
}

// ======================================================================
// k_mma: fp16 m16n8k16, BK=64, register double-buffer + ldmatrix
//   mode 0: z0 ic (2 segs -> g_ic, 1 scaled seg -> g_ic2)
//           z1 drive (2 segs -> g_drive) + qenh (1 seg -> g_qenh)
//   mode 1: syn 3-term (K=128) + rank-1 corr -> split write
// ======================================================================
#define BK 64
#define SMH 72                               // 64 + 8 pad (halfs)
#define OPH (128 * SMH)                      // halfs per operand per buffer
#define GSMEM (2 * 2 * OPH * 2)              // 2 bufs * (A+B) * bytes = 73728

__global__ __launch_bounds__(256, 1) void k_mma(int mode, const float* __restrict__ x,
                                                const float* __restrict__ cond) {
    extern __shared__ __align__(16) __half dsm[];
    __half (*smA)[OPH] = (__half (*)[OPH])dsm;             // [2][OPH]
    __half (*smB)[OPH] = (__half (*)[OPH])(dsm + 2 * OPH); // [2][OPH]
    __shared__ int s_noclip;
    const int tid = threadIdx.x, wid = tid >> 5, lane = tid & 31;
    const int m0 = blockIdx.y * 128, n0 = blockIdx.x * 128;
    const int wm0 = (wid & 1) * 64, wn0 = (wid >> 1) * 32;
    const int gr = lane >> 2, t4 = lane & 3;
    const int z = blockIdx.z;

    if (mode == 1) {
        if (wid == 0) {
            int nc = compute_noclip_warp(lane);
            if (lane == 0) s_noclip = nc;
        }
        __syncthreads();
        if (!s_noclip) {   // exact SIMT fallback (clip binds) — correctness path
            int m = m0 + (tid & 127), nh = tid >> 7;
            float s = 0.01f * g_ss[m];
            for (int n = n0 + nh * 64; n < n0 + nh * 64 + 64; ++n) {
                float acc = 0.f;
                for (int d = 0; d < DIN; ++d)
                    acc = fmaf(x[m * DIN + d], fminf(fmaxf(cond[d * HDIM + n] + s, 0.1f), 3.0f), acc);
                size_t o = (size_t)m * HDIM + n;
                h_split(acc, g_syn_hi[o], g_syn_lo[o], 1.f);
            }
            return;
        }
    }

    const __half *Aseg[3], *Bseg[3];
    float* Cf[3] = {nullptr, nullptr, nullptr};
    int ldA, ipern;
    if (mode == 0) {
        ldA = HDIM; ipern = 16;             // 1024 / BK
        if (z == 0) {
            Aseg[0] = g_syn_hi; Bseg[0] = g_WsT_hi;
            Aseg[1] = g_syn_lo; Bseg[1] = g_WsT_hi;
            Aseg[2] = g_syn_hi; Bseg[2] = g_WsT_lo;
            Cf[1] = g_ic; Cf[2] = g_ic2;
        } else {
            Aseg[0] = g_syn_hi; Bseg[0] = g_WlT;
            Aseg[1] = g_liqA;   Bseg[1] = g_WrT;
            Aseg[2] = g_qA;     Bseg[2] = g_WqlT;
            Cf[1] = g_drive; Cf[2] = g_qenh;
        }
    } else {
        ldA = DIN; ipern = 2;               // 128 / BK
        Aseg[0] = g_x_hi; Bseg[0] = g_cT_hi;
        Aseg[1] = g_x_lo; Bseg[1] = g_cT_hi;
        Aseg[2] = g_x_hi; Bseg[2] = g_cT_lo;
    }
    const int NT = 3 * ipern;

    // ldmatrix per-lane base addresses (byte, shared space)
    const uint32_t baseA = (uint32_t)__cvta_generic_to_shared(&smA[0][0]);
    const uint32_t baseB = (uint32_t)__cvta_generic_to_shared(&smB[0][0]);
    const uint32_t bufStride = (uint32_t)(OPH * 2);
    const uint32_t aLane = (uint32_t)(((wm0 + (lane & 15)) * SMH + 8 * (lane >> 4)) * 2);
    const uint32_t bLane = (uint32_t)(((wn0 + 8 * (lane >> 4) + (lane & 7)) * SMH + 8 * ((lane >> 3) & 1)) * 2);

    float acc[4][4][4];
    #pragma unroll
    for (int a = 0; a < 4; ++a)
        #pragma unroll
        for (int b = 0; b < 4; ++b)
            #pragma unroll
            for (int c = 0; c < 4; ++c) acc[a][b][c] = 0.f;

    const int lr = tid >> 3, lc8 = (tid & 7) * 8;    // 32 rows/pass, 8-half cols over BK=64
    uint4 ra[4], rb[4];
    {   // iter 0 -> buffer 0
        #pragma unroll
        for (int i = 0; i < 4; ++i) {
            int r = lr + i * 32;
            ra[i] = *(const uint4*)(Aseg[0] + (size_t)(m0 + r) * ldA + lc8);
            rb[i] = *(const uint4*)(Bseg[0] + (size_t)(n0 + r) * ldA + lc8);
        }
        #pragma unroll
        for (int i = 0; i < 4; ++i) {
            int r = lr + i * 32;
            *(uint4*)&smA[0][r * SMH + lc8] = ra[i];
            *(uint4*)&smB[0][r * SMH + lc8] = rb[i];
        }
    }
    __syncthreads();

    #pragma unroll 1
    for (int it = 0; it < NT; ++it) {
        const int cur = it & 1;
        const uint32_t aBuf = baseA + cur * bufStride + aLane;
        const uint32_t bBuf = baseB + cur * bufStride + bLane;
        if (it + 1 < NT) {
            int seg = (it + 1) / ipern, kk = ((it + 1) % ipern) * BK;
            #pragma unroll
            for (int i = 0; i < 4; ++i) {
                int r = lr + i * 32;
                ra[i] = *(const uint4*)(Aseg[seg] + (size_t)(m0 + r) * ldA + kk + lc8);
                rb[i] = *(const uint4*)(Bseg[seg] + (size_t)(n0 + r) * ldA + kk + lc8);
            }
        }
        #pragma unroll
        for (int kc = 0; kc < 4; ++kc) {
            const uint32_t kOff = (uint32_t)(kc * 32);   // 16 halfs = 32 bytes
            uint32_t af[4][4], bf[4][2];
            #pragma unroll
            for (int mt = 0; mt < 4; ++mt)
                ldsm4(af[mt][0], af[mt][1], af[mt][2], af[mt][3],
                      aBuf + (uint32_t)(mt * 16 * SMH * 2) + kOff);
            ldsm4(bf[0][0], bf[0][1], bf[1][0], bf[1][1], bBuf + kOff);
            ldsm4(bf[2][0], bf[2][1], bf[3][0], bf[3][1],
                  bBuf + (uint32_t)(16 * SMH * 2) + kOff);
            #pragma unroll
            for (int mt = 0; mt < 4; ++mt)
                #pragma unroll
                for (int nt = 0; nt < 4; ++nt)
                    mma16(acc[mt][nt], af[mt], bf[nt]);
        }
        if (mode == 0 && ((it + 1) % ipern == 0)) {
            float* C = Cf[it / ipern];
            if (C) {
                #pragma unroll
                for (int mt = 0; mt < 4; ++mt) {
                    int m = m0 + wm0 + mt * 16 + gr;
                    #pragma unroll
                    for (int nt = 0; nt < 4; ++nt) {
                        int n = n0 + wn0 + nt * 8 + t4 * 2;
                        *(float2*)(C + (size_t)m * HDIM + n) = make_float2(acc[mt][nt][0], acc[mt][nt][1]);
                        *(float2*)(C + (size_t)(m + 8) * HDIM + n) = make_float2(acc[mt][nt][2], acc[mt][nt][3]);
                    }
                }
                #pragma unroll
                for (int a = 0; a < 4; ++a)
                    #pragma unroll
                    for (int b = 0; b < 4; ++b)
                        #pragma unroll
                        for (int c = 0; c < 4; ++c) acc[a][b][c] = 0.f;
            }
        }
        if (it + 1 < NT) {
            #pragma unroll
            for (int i = 0; i < 4; ++i) {
                int r = lr + i * 32;
                *(uint4*)&smA[cur ^ 1][r * SMH + lc8] = ra[i];
                *(uint4*)&smB[cur ^ 1][r * SMH + lc8] = rb[i];
            }
        }
        __syncthreads();
    }

    if (mode == 1) {   // syn epilogue: rank-1 correction + fp16 split write
        #pragma unroll
        for (int mt = 0; mt < 4; ++mt) {
            int m = m0 + wm0 + mt * 16 + gr;
            float c0 = 0.01f * g_ss[m] * g_rs[m];
            float c1 = 0.01f * g_ss[m + 8] * g_rs[m + 8];
            #pragma unroll
            for (int nt = 0; nt < 4; ++nt) {
                int n = n0 + wn0 + nt * 8 + t4 * 2;
                #pragma unroll
                for (int e = 0; e < 4; ++e) {
                    int mm = (e < 2) ? m : m + 8;
                    float v = acc[mt][nt][e] + ((e < 2) ? c0 : c1);
                    size_t o = (size_t)mm * HDIM + n + (e & 1);
                    h_split(v, g_syn_hi[o], g_syn_lo[o], 1.f);
                }
            }
        }
    }
}

// ---------------- final fused epilogue: float4 vectorized ----------------
__global__ __launch_bounds__(256) void k_final(const float* __restrict__ mp,
                                               const float* __restrict__ refr_in,
                                               const float* __restrict__ liquid,
                                               const float* __restrict__ taup,
                                               const float* __restrict__ shist,
                                               float* __restrict__ out_fused,
                                               float* __restrict__ out_enh,
                                               float* __restrict__ out_mem,
                                               float* __restrict__ out_refr,
                                               float* __restrict__ out_hist) {
    __shared__ float wsum[8];
    const int b = blockIdx.x, tid = threadIdx.x;
    const float coh = expf(-0.00066666666666666664f);
    const int i4 = b * 256 + tid;

    float4 ic  = ((const float4*)g_ic)[i4];
    float4 ic2 = ((const float4*)g_ic2)[i4];
    float4 dr  = ((const float4*)g_drive)[i4];
    float4 qe  = ((const float4*)g_qenh)[i4];
    float4 mpv = ((const float4*)mp)[i4];
    float4 rf  = ((const float4*)refr_in)[i4];
    float4 lq  = ((const float4*)liquid)[i4];
    float4 tp  = ((const float4*)taup)[tid];

    float4 omem, orefr, oenh, ofused;
    float ssum = 0.f;
    #pragma unroll
    for (int e = 0; e < 4; ++e) {
        float icv = ((const float*)&ic)[e] + 9.765625e-4f * ((const float*)&ic2)[e];
        float r = fmaxf(((const float*)&rf)[e] - 0.1f, 0.f);
        bool act = (r == 0.f);
        float mem = ((const float*)&mpv)[e] * 0.95f + (act ? icv * 0.1f : 0.f);
        bool sp = (mem > 0.8f) && act;
        float spike = sp ? 1.f : 0.f;
        ((float*)&omem)[e] = sp ? 0.f : mem;
        ((float*)&orefr)[e] = sp ? 2.f : r;
        float sig = __fdividef(1.f, 1.f + __expf(-((const float*)&tp)[e]));
        float tau = 2.f + 23.f * sig;
        float l = ((const float*)&lq)[e];
        float nl = l + 0.1f * (tanh_fast(((const float*)&dr)[e]) - l) * __fdividef(1.f, tau);
        float enh = nl + 0.1f * (((const float*)&qe)[e] * coh * 0.85f);
        ((float*)&oenh)[e] = enh;
        ((float*)&ofused)[e] = spike * (1.f + 0.1f * tanh_fast(enh));
        ssum += spike;
    }
    ((float4*)out_mem)[i4] = omem;
    ((float4*)out_refr)[i4] = orefr;
    ((float4*)out_enh)[i4] = oenh;
    ((float4*)out_fused)[i4] = ofused;

    #pragma unroll
    for (int o = 16; o; o >>= 1) ssum += __shfl_xor_sync(~0u, ssum, o);
    if ((tid & 31) == 0) wsum[tid >> 5] = ssum;
    __syncthreads();
    if (tid < TLEN - 1) {
        out_hist[b * TLEN + tid] = shist[b * TLEN + tid + 1];
    } else if (tid == TLEN - 1) {
        float t = 0.f;
        #pragma unroll
        for (int i = 0; i < 8; ++i) t += wsum[i];
        out_hist[b * TLEN + TLEN - 1] = t * (1.0f / 1024.0f);
    }
}

// ---------------- launch ----------------
extern "C" void kernel_launch(void* const* d_in, const int* in_sizes, int n_in,
                              void* d_out, int out_size) {
    const float* x      = (const float*)d_in[0];
    const float* liquid = (const float*)d_in[1];
    const float* qstate = (const float*)d_in[2];
    const float* mp     = (const float*)d_in[3];
    const float* refr   = (const float*)d_in[4];
    const float* shist  = (const float*)d_in[5];
    const float* noise  = (const float*)d_in[6];
    const float* cond   = (const float*)d_in[7];
    const float* taup   = (const float*)d_in[8];
    const float* W_l    = (const float*)d_in[9];
    const float* W_r    = (const float*)d_in[10];
    const float* W_s    = (const float*)d_in[11];
    const float* W_ql   = (const float*)d_in[12];

    float* out       = (float*)d_out;
    float* out_fused = out;
    float* out_enh   = out + (size_t)BH;
    float* out_q     = out + (size_t)2 * BH;
    float* out_mem   = out + (size_t)3 * BH;
    float* out_refr  = out + (size_t)4 * BH;
    float* out_hist  = out + (size_t)5 * BH;

    static int smem_set = 0;
    if (!smem_set) {
        cudaFuncSetAttribute(k_mma, cudaFuncAttributeMaxDynamicSharedMemorySize, GSMEM);
        smem_set = 1;
    }

    k_prep<<<PREP_BLOCKS, 256>>>(x, liquid, qstate, noise, shist, cond,
                                 W_s, W_l, W_r, W_ql, out_q);
    k_mma<<<dim3(8, 8), 256, GSMEM>>>(1, x, cond);
    k_mma<<<dim3(8, 8, 2), 256, GSMEM>>>(0, x, cond);
    k_final<<<BDIM, 256>>>(mp, refr, liquid, taup, shist,
                           out_fused, out_enh, out_mem, out_refr, out_hist);
}